// round 2
// baseline (speedup 1.0000x reference)
#include <cuda_runtime.h>
#include <math.h>

#define N_NODES 100000
#define MAX_E   3200000
#define F_IN    128
#define F_HID   24
#define F_OUT   16

// ---------------- scratch (device globals; no allocation allowed) ------------
__device__ int   g_is64;                    // 1 if edge_index is int64
__device__ int   g_deg[N_NODES];
__device__ float g_dinv[N_NODES];
__device__ int   g_off[N_NODES + 1];
__device__ int   g_cursor[N_NODES];
__device__ int   g_blockSums[128];
__device__ int   g_csr[MAX_E];
__device__ float g_hs1[N_NODES * F_HID];   // (x@W1)*dinv
__device__ float g_hs2[N_NODES * F_OUT];   // (relu-layer1 @ W2)*dinv

// ---------------- dtype probe -------------------------------------------------
// int64 node ids < 2^31 have all-zero odd 32-bit words; int32 edge data has
// random values there. Sample 128 odd words (max word index 255, in-bounds for
// either interpretation since the buffer holds >= 6.4M 32-bit words).
__global__ void k_detect(const unsigned int* __restrict__ w) {
    int nz = 0;
    for (int i = threadIdx.x; i < 128; i += 32) nz |= (w[2 * i + 1] != 0u);
    unsigned any = __ballot_sync(0xffffffffu, nz);
    if (threadIdx.x == 0) g_is64 = (any == 0u) ? 1 : 0;
}

__device__ __forceinline__ int edge_at(const void* ei, int is64, long long idx) {
    return is64 ? (int)((const long long*)ei)[idx] : ((const int*)ei)[idx];
}

// ---------------- degree / normalization ------------------------------------
__global__ void k_init_deg() {
    int n = blockIdx.x * blockDim.x + threadIdx.x;
    if (n < N_NODES) g_deg[n] = 1;   // self-loop
}

__global__ void k_count_deg(const void* __restrict__ ei, int E) {
    int e = blockIdx.x * blockDim.x + threadIdx.x;
    if (e < E) {
        int dst = edge_at(ei, g_is64, e);       // row = dst
        atomicAdd(&g_deg[dst], 1);
    }
}

__global__ void k_dinv() {
    int n = blockIdx.x * blockDim.x + threadIdx.x;
    if (n < N_NODES) g_dinv[n] = rsqrtf((float)g_deg[n]);
}

// ---------------- exclusive scan of (deg-1) -> CSR offsets -------------------
__global__ void k_scan_block(int n) {
    __shared__ int s[1024];
    int gid = blockIdx.x * 1024 + threadIdx.x;
    int v = (gid < n) ? (g_deg[gid] - 1) : 0;
    s[threadIdx.x] = v;
    __syncthreads();
    for (int off = 1; off < 1024; off <<= 1) {
        int t = (threadIdx.x >= off) ? s[threadIdx.x - off] : 0;
        __syncthreads();
        s[threadIdx.x] += t;
        __syncthreads();
    }
    if (gid < n) g_off[gid] = s[threadIdx.x] - v;           // exclusive within block
    if (threadIdx.x == 1023) g_blockSums[blockIdx.x] = s[1023];
}

__global__ void k_scan_sums(int nb) {
    if (threadIdx.x == 0 && blockIdx.x == 0) {
        int acc = 0;
        for (int i = 0; i < nb; i++) { int t = g_blockSums[i]; g_blockSums[i] = acc; acc += t; }
    }
}

__global__ void k_scan_add(int n, int E) {
    int gid = blockIdx.x * blockDim.x + threadIdx.x;
    if (gid < n) {
        int v = g_off[gid] + g_blockSums[gid >> 10];
        g_off[gid] = v;
        g_cursor[gid] = v;
    }
    if (gid == 0) g_off[n] = E;
}

__global__ void k_fill_csr(const void* __restrict__ ei, int E) {
    int e = blockIdx.x * blockDim.x + threadIdx.x;
    if (e < E) {
        int is64 = g_is64;
        int dst = edge_at(ei, is64, e);                 // row
        int src = edge_at(ei, is64, (long long)E + e);  // col
        int slot = atomicAdd(&g_cursor[dst], 1);
        g_csr[slot] = src;
    }
}

// ---------------- GEMM1: hs1 = (x @ W1) * dinv  ------------------------------
__global__ __launch_bounds__(256) void k_gemm1(const float* __restrict__ x,
                                               const float* __restrict__ W1) {
    __shared__ __align__(16) float Ws[F_IN * F_HID];     // 12 KB
    __shared__ __align__(16) float xs[32 * F_IN];        // 16 KB
    int tid = threadIdx.x;
    for (int i = tid; i < F_IN * F_HID; i += 256) Ws[i] = W1[i];

    int base = blockIdx.x * 32;            // 3125 blocks * 32 = 100000 exactly
    const float4* xv = (const float4*)(x + (size_t)base * F_IN);
    float4* xsv = (float4*)xs;
    for (int i = tid; i < 32 * (F_IN / 4); i += 256) xsv[i] = xv[i];
    __syncthreads();

    int nloc = tid >> 3;                   // 0..31
    int jg = (tid & 7) * 3;                // 0,3,...,21
    int node = base + nloc;

    float a0 = 0.f, a1 = 0.f, a2 = 0.f;
    const float* xr = xs + nloc * F_IN;
    #pragma unroll
    for (int k = 0; k < F_IN; k++) {
        float xk = xr[k];
        a0 = fmaf(xk, Ws[k * F_HID + jg + 0], a0);
        a1 = fmaf(xk, Ws[k * F_HID + jg + 1], a1);
        a2 = fmaf(xk, Ws[k * F_HID + jg + 2], a2);
    }
    float dv = g_dinv[node];
    float* o = g_hs1 + (size_t)node * F_HID + jg;
    o[0] = a0 * dv; o[1] = a1 * dv; o[2] = a2 * dv;
}

// ---------------- layer1 gather + relu + GEMM2 fused -------------------------
__global__ __launch_bounds__(256) void k_gather1(const float* __restrict__ b1,
                                                 const float* __restrict__ W2) {
    __shared__ __align__(16) float W2s[F_HID * F_OUT];   // 1.5 KB
    __shared__ float b1s[F_HID];
    int tid = threadIdx.x;
    for (int i = tid; i < F_HID * F_OUT; i += 256) W2s[i] = W2[i];
    if (tid < F_HID) b1s[tid] = b1[tid];
    __syncthreads();

    int n = blockIdx.x * 256 + tid;
    if (n >= N_NODES) return;

    float4 acc[6];
    const float4* self = (const float4*)(g_hs1 + (size_t)n * F_HID);
    #pragma unroll
    for (int c = 0; c < 6; c++) acc[c] = self[c];   // self-loop term

    int s = g_off[n], e = g_off[n + 1];
    int i = s;
    for (; i + 1 < e; i += 2) {
        int s0 = g_csr[i], s1 = g_csr[i + 1];
        const float4* p0 = (const float4*)(g_hs1 + (size_t)s0 * F_HID);
        const float4* p1 = (const float4*)(g_hs1 + (size_t)s1 * F_HID);
        #pragma unroll
        for (int c = 0; c < 6; c++) {
            float4 v0 = p0[c], v1 = p1[c];
            acc[c].x += v0.x + v1.x; acc[c].y += v0.y + v1.y;
            acc[c].z += v0.z + v1.z; acc[c].w += v0.w + v1.w;
        }
    }
    if (i < e) {
        const float4* p0 = (const float4*)(g_hs1 + (size_t)g_csr[i] * F_HID);
        #pragma unroll
        for (int c = 0; c < 6; c++) {
            float4 v0 = p0[c];
            acc[c].x += v0.x; acc[c].y += v0.y; acc[c].z += v0.z; acc[c].w += v0.w;
        }
    }

    float dv = g_dinv[n];
    float h[F_HID];
    #pragma unroll
    for (int c = 0; c < 6; c++) {
        h[4*c+0] = acc[c].x; h[4*c+1] = acc[c].y; h[4*c+2] = acc[c].z; h[4*c+3] = acc[c].w;
    }
    #pragma unroll
    for (int j = 0; j < F_HID; j++) h[j] = fmaxf(fmaf(dv, h[j], b1s[j]), 0.f);

    float o[F_OUT];
    #pragma unroll
    for (int k = 0; k < F_OUT; k++) o[k] = 0.f;
    #pragma unroll
    for (int j = 0; j < F_HID; j++) {
        float hv = h[j];
        #pragma unroll
        for (int k = 0; k < F_OUT; k++) o[k] = fmaf(hv, W2s[j * F_OUT + k], o[k]);
    }
    float4* outp = (float4*)(g_hs2 + (size_t)n * F_OUT);
    #pragma unroll
    for (int c = 0; c < 4; c++) {
        float4 v; v.x = o[4*c+0]*dv; v.y = o[4*c+1]*dv; v.z = o[4*c+2]*dv; v.w = o[4*c+3]*dv;
        outp[c] = v;
    }
}

// ---------------- layer2 gather + bias + log_softmax -------------------------
__global__ __launch_bounds__(256) void k_gather2(const float* __restrict__ b2,
                                                 float* __restrict__ out) {
    __shared__ float b2s[F_OUT];
    int tid = threadIdx.x;
    if (tid < F_OUT) b2s[tid] = b2[tid];
    __syncthreads();

    int n = blockIdx.x * 256 + tid;
    if (n >= N_NODES) return;

    float4 acc[4];
    const float4* self = (const float4*)(g_hs2 + (size_t)n * F_OUT);
    #pragma unroll
    for (int c = 0; c < 4; c++) acc[c] = self[c];

    int s = g_off[n], e = g_off[n + 1];
    int i = s;
    for (; i + 1 < e; i += 2) {
        int s0 = g_csr[i], s1 = g_csr[i + 1];
        const float4* p0 = (const float4*)(g_hs2 + (size_t)s0 * F_OUT);
        const float4* p1 = (const float4*)(g_hs2 + (size_t)s1 * F_OUT);
        #pragma unroll
        for (int c = 0; c < 4; c++) {
            float4 v0 = p0[c], v1 = p1[c];
            acc[c].x += v0.x + v1.x; acc[c].y += v0.y + v1.y;
            acc[c].z += v0.z + v1.z; acc[c].w += v0.w + v1.w;
        }
    }
    if (i < e) {
        const float4* p0 = (const float4*)(g_hs2 + (size_t)g_csr[i] * F_OUT);
        #pragma unroll
        for (int c = 0; c < 4; c++) {
            float4 v0 = p0[c];
            acc[c].x += v0.x; acc[c].y += v0.y; acc[c].z += v0.z; acc[c].w += v0.w;
        }
    }

    float dv = g_dinv[n];
    float z[F_OUT];
    #pragma unroll
    for (int c = 0; c < 4; c++) {
        z[4*c+0] = fmaf(dv, acc[c].x, b2s[4*c+0]);
        z[4*c+1] = fmaf(dv, acc[c].y, b2s[4*c+1]);
        z[4*c+2] = fmaf(dv, acc[c].z, b2s[4*c+2]);
        z[4*c+3] = fmaf(dv, acc[c].w, b2s[4*c+3]);
    }
    float m = z[0];
    #pragma unroll
    for (int k = 1; k < F_OUT; k++) m = fmaxf(m, z[k]);
    float sum = 0.f;
    #pragma unroll
    for (int k = 0; k < F_OUT; k++) sum += __expf(z[k] - m);
    float lse = m + __logf(sum);

    float4* outp = (float4*)(out + (size_t)n * F_OUT);
    #pragma unroll
    for (int c = 0; c < 4; c++) {
        float4 v;
        v.x = z[4*c+0] - lse; v.y = z[4*c+1] - lse;
        v.z = z[4*c+2] - lse; v.w = z[4*c+3] - lse;
        outp[c] = v;
    }
}

// ---------------- launch ------------------------------------------------------
extern "C" void kernel_launch(void* const* d_in, const int* in_sizes, int n_in,
                              void* d_out, int out_size) {
    const float* x  = (const float*)d_in[0];
    const void*  ei = d_in[1];
    const float* W1 = (const float*)d_in[2];
    const float* b1 = (const float*)d_in[3];
    const float* W2 = (const float*)d_in[4];
    const float* b2 = (const float*)d_in[5];
    float* out = (float*)d_out;

    int E = in_sizes[1] / 2;
    if (E > MAX_E) E = MAX_E;

    const int NB  = (N_NODES + 255) / 256;     // 391
    const int EB  = (E + 255) / 256;
    const int SB  = (N_NODES + 1023) / 1024;   // 98

    k_detect<<<1, 32>>>((const unsigned int*)ei);
    k_init_deg<<<NB, 256>>>();
    k_count_deg<<<EB, 256>>>(ei, E);
    k_dinv<<<NB, 256>>>();
    k_scan_block<<<SB, 1024>>>(N_NODES);
    k_scan_sums<<<1, 32>>>(SB);
    k_scan_add<<<NB, 256>>>(N_NODES, E);
    k_fill_csr<<<EB, 256>>>(ei, E);
    k_gemm1<<<N_NODES / 32, 256>>>(x, W1);
    k_gather1<<<NB, 256>>>(b1, W2);
    k_gather2<<<NB, 256>>>(b2, out);
}

// round 3
// speedup vs baseline: 1.3132x; 1.3132x over previous
#include <cuda_runtime.h>
#include <math.h>

#define N_NODES 100000
#define MAX_E   3200000
#define F_IN    128
#define F_HID   24
#define F_OUT   16
#define HID_PAD 32     // padded row stride for hs1 (128B lines)

// ---------------- scratch (device globals; no allocation allowed) ------------
__device__ int   g_is64;                    // 1 if edge_index is int64
__device__ int   g_deg[N_NODES];
__device__ float g_dinv[N_NODES];
__device__ int   g_off[N_NODES + 1];
__device__ int   g_cursor[N_NODES];
__device__ int   g_blockSums[128];
__device__ int   g_csr[MAX_E];
__device__ float g_hs1p[N_NODES * HID_PAD];  // (x@W1)*dinv, padded to 32 floats
__device__ float g_hs2[N_NODES * F_OUT];     // (relu-layer1 @ W2)*dinv

// ---------------- dtype probe + degree init ----------------------------------
// int64 node ids < 2^31 have all-zero odd 32-bit words; int32 edge data has
// random values there.
__global__ void k_detect_init(const unsigned int* __restrict__ w) {
    int n = blockIdx.x * blockDim.x + threadIdx.x;
    if (n < N_NODES) g_deg[n] = 1;   // self-loop
    if (blockIdx.x == 0 && threadIdx.x < 32) {
        int nz = 0;
        for (int i = threadIdx.x; i < 128; i += 32) nz |= (w[2 * i + 1] != 0u);
        unsigned any = __ballot_sync(0xffffffffu, nz);
        if (threadIdx.x == 0) g_is64 = (any == 0u) ? 1 : 0;
    }
}

__device__ __forceinline__ int edge_at(const void* ei, int is64, long long idx) {
    return is64 ? (int)((const long long*)ei)[idx] : ((const int*)ei)[idx];
}

__global__ void k_count_deg(const void* __restrict__ ei, int E) {
    int e = blockIdx.x * blockDim.x + threadIdx.x;
    if (e < E) atomicAdd(&g_deg[edge_at(ei, g_is64, e)], 1);
}

// ---------------- exclusive scan of (deg-1) -> CSR offsets (+ dinv) ----------
__global__ void k_scan_block(int n) {
    __shared__ int s[1024];
    int gid = blockIdx.x * 1024 + threadIdx.x;
    int deg = (gid < n) ? g_deg[gid] : 1;
    int v = deg - 1;
    s[threadIdx.x] = v;
    __syncthreads();
    for (int off = 1; off < 1024; off <<= 1) {
        int t = (threadIdx.x >= off) ? s[threadIdx.x - off] : 0;
        __syncthreads();
        s[threadIdx.x] += t;
        __syncthreads();
    }
    if (gid < n) {
        g_off[gid] = s[threadIdx.x] - v;     // exclusive within block
        g_dinv[gid] = rsqrtf((float)deg);
    }
    if (threadIdx.x == 1023) g_blockSums[blockIdx.x] = s[1023];
}

__global__ void k_scan_sums(int nb) {
    if (threadIdx.x == 0) {
        int acc = 0;
        for (int i = 0; i < nb; i++) { int t = g_blockSums[i]; g_blockSums[i] = acc; acc += t; }
    }
}

__global__ void k_scan_add(int n, int E) {
    int gid = blockIdx.x * blockDim.x + threadIdx.x;
    if (gid < n) {
        int v = g_off[gid] + g_blockSums[gid >> 10];
        g_off[gid] = v;
        g_cursor[gid] = v;
    }
    if (gid == 0) g_off[n] = E;
}

__global__ void k_fill_csr(const void* __restrict__ ei, int E) {
    int e = blockIdx.x * blockDim.x + threadIdx.x;
    if (e < E) {
        int is64 = g_is64;
        int dst = edge_at(ei, is64, e);                 // row
        int src = edge_at(ei, is64, (long long)E + e);  // col
        int slot = atomicAdd(&g_cursor[dst], 1);
        g_csr[slot] = src;
    }
}

// ---------------- GEMM1: hs1p = (x @ W1) * dinv (padded rows) ----------------
__global__ __launch_bounds__(256) void k_gemm1(const float* __restrict__ x,
                                               const float* __restrict__ W1) {
    __shared__ __align__(16) float Ws[F_IN * F_HID];     // 12 KB
    __shared__ __align__(16) float xs[32 * F_IN];        // 16 KB
    int tid = threadIdx.x;
    for (int i = tid; i < F_IN * F_HID; i += 256) Ws[i] = W1[i];

    int base = blockIdx.x * 32;            // 3125 blocks * 32 = 100000 exactly
    const float4* xv = (const float4*)(x + (size_t)base * F_IN);
    float4* xsv = (float4*)xs;
    for (int i = tid; i < 32 * (F_IN / 4); i += 256) xsv[i] = xv[i];
    __syncthreads();

    int nloc = tid >> 3;                   // 0..31
    int jg = (tid & 7) * 3;                // 0,3,...,21
    int node = base + nloc;

    float a0 = 0.f, a1 = 0.f, a2 = 0.f;
    const float* xr = xs + nloc * F_IN;
    #pragma unroll
    for (int k = 0; k < F_IN; k++) {
        float xk = xr[k];
        a0 = fmaf(xk, Ws[k * F_HID + jg + 0], a0);
        a1 = fmaf(xk, Ws[k * F_HID + jg + 1], a1);
        a2 = fmaf(xk, Ws[k * F_HID + jg + 2], a2);
    }
    float dv = g_dinv[node];
    float* o = g_hs1p + (size_t)node * HID_PAD + jg;
    o[0] = a0 * dv; o[1] = a1 * dv; o[2] = a2 * dv;
    if ((tid & 7) == 7) {                  // zero the pad [24..31]
        float4 z4 = make_float4(0.f, 0.f, 0.f, 0.f);
        *(float4*)(g_hs1p + (size_t)node * HID_PAD + 24) = z4;
        *(float4*)(g_hs1p + (size_t)node * HID_PAD + 28) = z4;
    }
}

// ---------------- layer1 gather (8 lanes/node, coalesced) + relu + GEMM2 -----
__global__ __launch_bounds__(256) void k_gather1(const float* __restrict__ b1,
                                                 const float* __restrict__ W2) {
    __shared__ float W2s[F_HID * F_OUT];   // 384 floats
    int tid = threadIdx.x;
    for (int i = tid; i < F_HID * F_OUT; i += 256) W2s[i] = W2[i];
    __syncthreads();

    int lane = tid & 31;
    int l = lane & 7;                       // 0..7 : float4 slot within padded row
    int node = blockIdx.x * 32 + (tid >> 3);  // 3125 blocks * 32 nodes = exact

    const float4* base = (const float4*)g_hs1p;
    float4 acc = base[node * 8 + l];        // self-loop term
    int s = g_off[node], e = g_off[node + 1];
    int i = s;
    for (; i + 3 < e; i += 4) {
        int s0 = g_csr[i], s1 = g_csr[i+1], s2 = g_csr[i+2], s3 = g_csr[i+3];
        float4 v0 = base[s0 * 8 + l], v1 = base[s1 * 8 + l];
        float4 v2 = base[s2 * 8 + l], v3 = base[s3 * 8 + l];
        acc.x += (v0.x + v1.x) + (v2.x + v3.x);
        acc.y += (v0.y + v1.y) + (v2.y + v3.y);
        acc.z += (v0.z + v1.z) + (v2.z + v3.z);
        acc.w += (v0.w + v1.w) + (v2.w + v3.w);
    }
    for (; i < e; i++) {
        float4 v0 = base[g_csr[i] * 8 + l];
        acc.x += v0.x; acc.y += v0.y; acc.z += v0.z; acc.w += v0.w;
    }

    float dv = g_dinv[node];
    float h0 = 0.f, h1 = 0.f, h2 = 0.f, h3 = 0.f;
    if (l < 6) {
        h0 = fmaxf(fmaf(dv, acc.x, b1[l*4+0]), 0.f);
        h1 = fmaxf(fmaf(dv, acc.y, b1[l*4+1]), 0.f);
        h2 = fmaxf(fmaf(dv, acc.z, b1[l*4+2]), 0.f);
        h3 = fmaxf(fmaf(dv, acc.w, b1[l*4+3]), 0.f);
    }

    // GEMM2: lane computes output cols {2l, 2l+1}; h broadcast via shuffles
    float o0 = 0.f, o1 = 0.f;
    int gbase = lane & ~7;                  // first lane of this node's group
    #pragma unroll
    for (int j = 0; j < F_HID; j++) {
        float hsrc = ((j & 3) == 0) ? h0 : ((j & 3) == 1) ? h1 : ((j & 3) == 2) ? h2 : h3;
        float hj = __shfl_sync(0xffffffffu, hsrc, gbase + (j >> 2));
        o0 = fmaf(hj, W2s[j * F_OUT + l*2 + 0], o0);
        o1 = fmaf(hj, W2s[j * F_OUT + l*2 + 1], o1);
    }
    g_hs2[(size_t)node * F_OUT + l*2 + 0] = o0 * dv;
    g_hs2[(size_t)node * F_OUT + l*2 + 1] = o1 * dv;
}

// ---------------- layer2 gather (4 lanes/node) + bias + log_softmax ----------
__global__ __launch_bounds__(256) void k_gather2(const float* __restrict__ b2,
                                                 float* __restrict__ out) {
    int tid = threadIdx.x;
    int lane = tid & 31;
    int l = lane & 3;                       // float4 slot within 16-float row
    int node = blockIdx.x * 64 + (tid >> 2);
    int nc = (node < N_NODES) ? node : (N_NODES - 1);   // clamp for tail; shuffles stay full-warp

    const float4* base = (const float4*)g_hs2;
    float4 acc = base[nc * 4 + l];          // self-loop term
    int s = g_off[nc], e = g_off[nc + 1];
    int i = s;
    for (; i + 3 < e; i += 4) {
        int s0 = g_csr[i], s1 = g_csr[i+1], s2 = g_csr[i+2], s3 = g_csr[i+3];
        float4 v0 = base[s0 * 4 + l], v1 = base[s1 * 4 + l];
        float4 v2 = base[s2 * 4 + l], v3 = base[s3 * 4 + l];
        acc.x += (v0.x + v1.x) + (v2.x + v3.x);
        acc.y += (v0.y + v1.y) + (v2.y + v3.y);
        acc.z += (v0.z + v1.z) + (v2.z + v3.z);
        acc.w += (v0.w + v1.w) + (v2.w + v3.w);
    }
    for (; i < e; i++) {
        float4 v0 = base[g_csr[i] * 4 + l];
        acc.x += v0.x; acc.y += v0.y; acc.z += v0.z; acc.w += v0.w;
    }

    float dv = g_dinv[nc];
    float z0 = fmaf(dv, acc.x, b2[l*4+0]);
    float z1 = fmaf(dv, acc.y, b2[l*4+1]);
    float z2 = fmaf(dv, acc.z, b2[l*4+2]);
    float z3 = fmaf(dv, acc.w, b2[l*4+3]);

    float m = fmaxf(fmaxf(z0, z1), fmaxf(z2, z3));
    m = fmaxf(m, __shfl_xor_sync(0xffffffffu, m, 1));
    m = fmaxf(m, __shfl_xor_sync(0xffffffffu, m, 2));
    float sum = __expf(z0 - m) + __expf(z1 - m) + __expf(z2 - m) + __expf(z3 - m);
    sum += __shfl_xor_sync(0xffffffffu, sum, 1);
    sum += __shfl_xor_sync(0xffffffffu, sum, 2);
    float lse = m + __logf(sum);

    if (node < N_NODES) {
        float4 v; v.x = z0 - lse; v.y = z1 - lse; v.z = z2 - lse; v.w = z3 - lse;
        ((float4*)out)[node * 4 + l] = v;
    }
}

// ---------------- launch ------------------------------------------------------
extern "C" void kernel_launch(void* const* d_in, const int* in_sizes, int n_in,
                              void* d_out, int out_size) {
    const float* x  = (const float*)d_in[0];
    const void*  ei = d_in[1];
    const float* W1 = (const float*)d_in[2];
    const float* b1 = (const float*)d_in[3];
    const float* W2 = (const float*)d_in[4];
    const float* b2 = (const float*)d_in[5];
    float* out = (float*)d_out;

    int E = in_sizes[1] / 2;
    if (E > MAX_E) E = MAX_E;

    const int NB = (N_NODES + 255) / 256;     // 391
    const int EB = (E + 255) / 256;
    const int SB = (N_NODES + 1023) / 1024;   // 98

    k_detect_init<<<NB, 256>>>((const unsigned int*)ei);
    k_count_deg<<<EB, 256>>>(ei, E);
    k_scan_block<<<SB, 1024>>>(N_NODES);
    k_scan_sums<<<1, 32>>>(SB);
    k_scan_add<<<NB, 256>>>(N_NODES, E);
    k_fill_csr<<<EB, 256>>>(ei, E);
    k_gemm1<<<N_NODES / 32, 256>>>(x, W1);
    k_gather1<<<N_NODES / 32, 256>>>(b1, W2);
    k_gather2<<<(N_NODES + 63) / 64, 256>>>(b2, out);
}

// round 4
// speedup vs baseline: 1.4132x; 1.0762x over previous
#include <cuda_runtime.h>
#include <cuda_fp16.h>
#include <math.h>

#define N_NODES 100000
#define MAX_E   3200000
#define F_IN    128
#define F_HID   24
#define F_OUT   16
#define HID_PAD 32     // padded half-row stride for hs1 (64B lines)

// ---------------- scratch (device globals; no allocation allowed) ------------
__device__ int    g_is64;                    // 1 if edge_index is int64
__device__ int    g_deg[N_NODES];
__device__ float  g_dinv[N_NODES];
__device__ int    g_off[N_NODES + 1];
__device__ int    g_cursor[N_NODES];
__device__ int    g_blockSums[128];          // raw per-block totals
__device__ int    g_csr[MAX_E];
__device__ __half g_hs1h[N_NODES * HID_PAD]; // (x@W1)*dinv, fp16, 64B rows
__device__ __half g_hs2h[N_NODES * F_OUT];   // (relu-l1 @ W2)*dinv, fp16, 32B rows

// ---------------- dtype probe + degree init ----------------------------------
__global__ void k_detect_init(const unsigned int* __restrict__ w) {
    int n = blockIdx.x * blockDim.x + threadIdx.x;
    if (n < N_NODES) g_deg[n] = 1;   // self-loop
    if (blockIdx.x == 0 && threadIdx.x < 32) {
        int nz = 0;
        for (int i = threadIdx.x; i < 128; i += 32) nz |= (w[2 * i + 1] != 0u);
        unsigned any = __ballot_sync(0xffffffffu, nz);
        if (threadIdx.x == 0) g_is64 = (any == 0u) ? 1 : 0;
    }
}

__device__ __forceinline__ int edge_at(const void* ei, int is64, long long idx) {
    return is64 ? (int)((const long long*)ei)[idx] : ((const int*)ei)[idx];
}

__global__ void k_count_deg(const void* __restrict__ ei, int E) {
    int e = blockIdx.x * blockDim.x + threadIdx.x;
    if (e < E) atomicAdd(&g_deg[edge_at(ei, g_is64, e)], 1);
}

// ---------------- exclusive scan of (deg-1) -> CSR offsets (+ dinv) ----------
__global__ void k_scan_block(int n) {
    __shared__ int s[1024];
    int gid = blockIdx.x * 1024 + threadIdx.x;
    int deg = (gid < n) ? g_deg[gid] : 1;
    int v = deg - 1;
    s[threadIdx.x] = v;
    __syncthreads();
    for (int off = 1; off < 1024; off <<= 1) {
        int t = (threadIdx.x >= off) ? s[threadIdx.x - off] : 0;
        __syncthreads();
        s[threadIdx.x] += t;
        __syncthreads();
    }
    if (gid < n) {
        g_off[gid] = s[threadIdx.x] - v;     // exclusive within block
        g_dinv[gid] = rsqrtf((float)deg);
    }
    if (threadIdx.x == 1023) g_blockSums[blockIdx.x] = s[1023];
}

// fused: per-block prefix over g_blockSums (region <= 98) + add + cursor init
__global__ void k_scan_add(int n, int E) {
    __shared__ int sbase;
    int region = (blockIdx.x * 256) >> 10;   // 256 divides 1024: block in one region
    if (threadIdx.x < 32) {
        int acc = 0;
        for (int i = threadIdx.x; i < region; i += 32) acc += g_blockSums[i];
        #pragma unroll
        for (int o = 16; o; o >>= 1) acc += __shfl_xor_sync(0xffffffffu, acc, o);
        if (threadIdx.x == 0) sbase = acc;
    }
    __syncthreads();
    int gid = blockIdx.x * 256 + threadIdx.x;
    if (gid < n) {
        int v = g_off[gid] + sbase;
        g_off[gid] = v;
        g_cursor[gid] = v;
    }
    if (gid == 0) g_off[n] = E;
}

__global__ void k_fill_csr(const void* __restrict__ ei, int E) {
    int e = blockIdx.x * blockDim.x + threadIdx.x;
    if (e < E) {
        int is64 = g_is64;
        int dst = edge_at(ei, is64, e);                 // row
        int src = edge_at(ei, is64, (long long)E + e);  // col
        int slot = atomicAdd(&g_cursor[dst], 1);
        g_csr[slot] = src;
    }
}

// ---------------- GEMM1: hs1h = fp16((x @ W1) * dinv), padded rows -----------
// 4 threads/node, 6 outputs each; 64 nodes/block.
__global__ __launch_bounds__(256) void k_gemm1(const float* __restrict__ x,
                                               const float* __restrict__ W1) {
    __shared__ float Ws[F_IN * F_HID];                   // 12 KB
    __shared__ __align__(16) float xs[64 * F_IN];        // 32 KB
    int tid = threadIdx.x;
    for (int i = tid; i < F_IN * F_HID; i += 256) Ws[i] = W1[i];

    int base = blockIdx.x * 64;
    int nvalid = N_NODES - base; if (nvalid > 64) nvalid = 64;
    const float4* xv = (const float4*)(x + (size_t)base * F_IN);
    float4* xsv = (float4*)xs;
    int nv4 = nvalid * (F_IN / 4);
    for (int i = tid; i < nv4; i += 256) xsv[i] = xv[i];
    __syncthreads();

    int nloc = tid >> 2;                   // 0..63
    int l = tid & 3;
    int node = base + nloc;
    if (node >= N_NODES) return;

    float a[6] = {0.f, 0.f, 0.f, 0.f, 0.f, 0.f};
    const float* xr = xs + nloc * F_IN;
    #pragma unroll
    for (int k = 0; k < F_IN; k++) {
        float xk = xr[k];
        #pragma unroll
        for (int m = 0; m < 6; m++) a[m] = fmaf(xk, Ws[k * F_HID + l * 6 + m], a[m]);
    }
    float dv = g_dinv[node];
    __half2* o = (__half2*)(g_hs1h + (size_t)node * HID_PAD + l * 6);
    o[0] = __floats2half2_rn(a[0] * dv, a[1] * dv);
    o[1] = __floats2half2_rn(a[2] * dv, a[3] * dv);
    o[2] = __floats2half2_rn(a[4] * dv, a[5] * dv);
    if (l == 3) {                          // zero pad halfs [24..32)
        uint4 z = make_uint4(0u, 0u, 0u, 0u);
        *(uint4*)(g_hs1h + (size_t)node * HID_PAD + 24) = z;
    }
}

__device__ __forceinline__ void add8(float* acc, uint4 v) {
    __half2* hp = (__half2*)&v;
    #pragma unroll
    for (int c = 0; c < 4; c++) {
        float2 f = __half22float2(hp[c]);
        acc[2*c]   += f.x;
        acc[2*c+1] += f.y;
    }
}

// ---------------- layer1 gather (4 lanes/node, 16B each) + relu + GEMM2 ------
__global__ __launch_bounds__(256) void k_gather1(const float* __restrict__ b1,
                                                 const float* __restrict__ W2) {
    __shared__ float W2s[F_HID * F_OUT];
    __shared__ float b1s[F_HID];
    int tid = threadIdx.x;
    for (int i = tid; i < F_HID * F_OUT; i += 256) W2s[i] = W2[i];
    if (tid < F_HID) b1s[tid] = b1[tid];
    __syncthreads();

    int lane = tid & 31;
    int l = lane & 3;                      // uint4 slot within 32-half row
    int node = blockIdx.x * 64 + (tid >> 2);
    int nc = (node < N_NODES) ? node : (N_NODES - 1);

    const uint4* base = (const uint4*)g_hs1h;    // row = 4 x uint4
    float acc[8];
    {
        uint4 sv = base[(size_t)nc * 4 + l];     // self-loop term
        __half2* hp = (__half2*)&sv;
        #pragma unroll
        for (int c = 0; c < 4; c++) {
            float2 f = __half22float2(hp[c]);
            acc[2*c] = f.x; acc[2*c+1] = f.y;
        }
    }
    int s = g_off[nc], e = g_off[nc + 1];
    int i = s;
    for (; i + 3 < e; i += 4) {
        int s0 = g_csr[i], s1 = g_csr[i+1], s2 = g_csr[i+2], s3 = g_csr[i+3];
        uint4 v0 = base[(size_t)s0 * 4 + l];
        uint4 v1 = base[(size_t)s1 * 4 + l];
        uint4 v2 = base[(size_t)s2 * 4 + l];
        uint4 v3 = base[(size_t)s3 * 4 + l];
        add8(acc, v0); add8(acc, v1); add8(acc, v2); add8(acc, v3);
    }
    for (; i < e; i++) add8(acc, base[(size_t)g_csr[i] * 4 + l]);

    float dv = g_dinv[nc];
    float h[8];
    if (l < 3) {
        #pragma unroll
        for (int k = 0; k < 8; k++)
            h[k] = fmaxf(fmaf(dv, acc[k], b1s[l * 8 + k]), 0.f);
    } else {
        #pragma unroll
        for (int k = 0; k < 8; k++) h[k] = 0.f;
    }

    // GEMM2: lane computes output cols 4l..4l+3; h broadcast via shuffles
    float o0 = 0.f, o1 = 0.f, o2 = 0.f, o3 = 0.f;
    int gbase = lane & ~3;
    #pragma unroll
    for (int j = 0; j < F_HID; j++) {
        float hj = __shfl_sync(0xffffffffu, h[j & 7], gbase + (j >> 3));
        o0 = fmaf(hj, W2s[j * F_OUT + l*4 + 0], o0);
        o1 = fmaf(hj, W2s[j * F_OUT + l*4 + 1], o1);
        o2 = fmaf(hj, W2s[j * F_OUT + l*4 + 2], o2);
        o3 = fmaf(hj, W2s[j * F_OUT + l*4 + 3], o3);
    }
    if (node < N_NODES) {
        __half2* op = (__half2*)(g_hs2h + (size_t)node * F_OUT + l * 4);
        op[0] = __floats2half2_rn(o0 * dv, o1 * dv);
        op[1] = __floats2half2_rn(o2 * dv, o3 * dv);
    }
}

// ---------------- layer2 gather (2 lanes/node, 16B each) + log_softmax -------
__global__ __launch_bounds__(256) void k_gather2(const float* __restrict__ b2,
                                                 float* __restrict__ out) {
    __shared__ float b2s[F_OUT];
    if (threadIdx.x < F_OUT) b2s[threadIdx.x] = b2[threadIdx.x];
    __syncthreads();

    int tid = threadIdx.x;
    int lane = tid & 31;
    int l = lane & 1;                      // uint4 slot within 16-half row
    int node = blockIdx.x * 128 + (tid >> 1);
    int nc = (node < N_NODES) ? node : (N_NODES - 1);

    const uint4* base = (const uint4*)g_hs2h;    // row = 2 x uint4
    float acc[8];
    {
        uint4 sv = base[(size_t)nc * 2 + l];
        __half2* hp = (__half2*)&sv;
        #pragma unroll
        for (int c = 0; c < 4; c++) {
            float2 f = __half22float2(hp[c]);
            acc[2*c] = f.x; acc[2*c+1] = f.y;
        }
    }
    int s = g_off[nc], e = g_off[nc + 1];
    int i = s;
    for (; i + 3 < e; i += 4) {
        int s0 = g_csr[i], s1 = g_csr[i+1], s2 = g_csr[i+2], s3 = g_csr[i+3];
        uint4 v0 = base[(size_t)s0 * 2 + l];
        uint4 v1 = base[(size_t)s1 * 2 + l];
        uint4 v2 = base[(size_t)s2 * 2 + l];
        uint4 v3 = base[(size_t)s3 * 2 + l];
        add8(acc, v0); add8(acc, v1); add8(acc, v2); add8(acc, v3);
    }
    for (; i < e; i++) add8(acc, base[(size_t)g_csr[i] * 2 + l]);

    float dv = g_dinv[nc];
    float z[8];
    #pragma unroll
    for (int k = 0; k < 8; k++) z[k] = fmaf(dv, acc[k], b2s[l * 8 + k]);

    float m = z[0];
    #pragma unroll
    for (int k = 1; k < 8; k++) m = fmaxf(m, z[k]);
    m = fmaxf(m, __shfl_xor_sync(0xffffffffu, m, 1));
    float sum = 0.f;
    #pragma unroll
    for (int k = 0; k < 8; k++) sum += __expf(z[k] - m);
    sum += __shfl_xor_sync(0xffffffffu, sum, 1);
    float lse = m + __logf(sum);

    if (node < N_NODES) {
        float4* outp = (float4*)out + (size_t)node * 4 + l * 2;
        float4 w0, w1;
        w0.x = z[0] - lse; w0.y = z[1] - lse; w0.z = z[2] - lse; w0.w = z[3] - lse;
        w1.x = z[4] - lse; w1.y = z[5] - lse; w1.z = z[6] - lse; w1.w = z[7] - lse;
        outp[0] = w0; outp[1] = w1;
    }
}

// ---------------- launch ------------------------------------------------------
extern "C" void kernel_launch(void* const* d_in, const int* in_sizes, int n_in,
                              void* d_out, int out_size) {
    const float* x  = (const float*)d_in[0];
    const void*  ei = d_in[1];
    const float* W1 = (const float*)d_in[2];
    const float* b1 = (const float*)d_in[3];
    const float* W2 = (const float*)d_in[4];
    const float* b2 = (const float*)d_in[5];
    float* out = (float*)d_out;

    int E = in_sizes[1] / 2;
    if (E > MAX_E) E = MAX_E;

    const int NB = (N_NODES + 255) / 256;     // 391
    const int EB = (E + 255) / 256;
    const int SB = (N_NODES + 1023) / 1024;   // 98

    k_detect_init<<<NB, 256>>>((const unsigned int*)ei);
    k_count_deg<<<EB, 256>>>(ei, E);
    k_scan_block<<<SB, 1024>>>(N_NODES);
    k_scan_add<<<NB, 256>>>(N_NODES, E);
    k_fill_csr<<<EB, 256>>>(ei, E);
    k_gemm1<<<(N_NODES + 63) / 64, 256>>>(x, W1);
    k_gather1<<<(N_NODES + 63) / 64, 256>>>(b1, W2);
    k_gather2<<<(N_NODES + 127) / 128, 256>>>(b2, out);
}

// round 5
// speedup vs baseline: 1.4287x; 1.0110x over previous
#include <cuda_runtime.h>
#include <cuda_fp16.h>
#include <math.h>

#define N_NODES 100000
#define MAX_E   3200000
#define F_IN    128
#define F_HID   24
#define F_OUT   16
#define HID_PAD 32     // padded half-row stride for hs1 (64B lines)

// ---------------- scratch (device globals; no allocation allowed) ------------
__device__ int    g_is64;                    // 1 if edge_index is int64
__device__ int    g_deg[N_NODES];
__device__ float  g_dinv[N_NODES];
__device__ int    g_off[N_NODES + 1];
__device__ int    g_cursor[N_NODES];
__device__ int    g_blockSums[128];          // raw per-block totals
__device__ int    g_csr[MAX_E];
__device__ __half g_hs1h[N_NODES * HID_PAD]; // (x@W1)*dinv, fp16, 64B rows
__device__ __half g_hs2h[N_NODES * F_OUT];   // (relu-l1 @ W2)*dinv, fp16, 32B rows

// ---------------- dtype probe + degree init ----------------------------------
__global__ void k_detect_init(const unsigned int* __restrict__ w) {
    int n = blockIdx.x * blockDim.x + threadIdx.x;
    if (n < N_NODES) g_deg[n] = 1;   // self-loop
    if (blockIdx.x == 0 && threadIdx.x < 32) {
        int nz = 0;
        for (int i = threadIdx.x; i < 128; i += 32) nz |= (w[2 * i + 1] != 0u);
        unsigned any = __ballot_sync(0xffffffffu, nz);
        if (threadIdx.x == 0) g_is64 = (any == 0u) ? 1 : 0;
    }
}

__device__ __forceinline__ int edge_at(const void* ei, int is64, long long idx) {
    return is64 ? (int)((const long long*)ei)[idx] : ((const int*)ei)[idx];
}

__global__ void k_count_deg(const void* __restrict__ ei, int E) {
    int e = blockIdx.x * blockDim.x + threadIdx.x;
    if (e < E) atomicAdd(&g_deg[edge_at(ei, g_is64, e)], 1);
}

// ---------------- exclusive scan of (deg-1) -> CSR offsets (+ dinv) ----------
__global__ void k_scan_block(int n) {
    __shared__ int s[1024];
    int gid = blockIdx.x * 1024 + threadIdx.x;
    int deg = (gid < n) ? g_deg[gid] : 1;
    int v = deg - 1;
    s[threadIdx.x] = v;
    __syncthreads();
    for (int off = 1; off < 1024; off <<= 1) {
        int t = (threadIdx.x >= off) ? s[threadIdx.x - off] : 0;
        __syncthreads();
        s[threadIdx.x] += t;
        __syncthreads();
    }
    if (gid < n) {
        g_off[gid] = s[threadIdx.x] - v;     // exclusive within block
        g_dinv[gid] = rsqrtf((float)deg);
    }
    if (threadIdx.x == 1023) g_blockSums[blockIdx.x] = s[1023];
}

// fused: per-block prefix over g_blockSums (region <= 98) + add + cursor init
__global__ void k_scan_add(int n, int E) {
    __shared__ int sbase;
    int region = (blockIdx.x * 256) >> 10;   // 256 divides 1024: block in one region
    if (threadIdx.x < 32) {
        int acc = 0;
        for (int i = threadIdx.x; i < region; i += 32) acc += g_blockSums[i];
        #pragma unroll
        for (int o = 16; o; o >>= 1) acc += __shfl_xor_sync(0xffffffffu, acc, o);
        if (threadIdx.x == 0) sbase = acc;
    }
    __syncthreads();
    int gid = blockIdx.x * 256 + threadIdx.x;
    if (gid < n) {
        int v = g_off[gid] + sbase;
        g_off[gid] = v;
        g_cursor[gid] = v;
    }
    if (gid == 0) g_off[n] = E;
}

__global__ void k_fill_csr(const void* __restrict__ ei, int E) {
    int e = blockIdx.x * blockDim.x + threadIdx.x;
    if (e < E) {
        int is64 = g_is64;
        int dst = edge_at(ei, is64, e);                 // row
        int src = edge_at(ei, is64, (long long)E + e);  // col
        int slot = atomicAdd(&g_cursor[dst], 1);
        g_csr[slot] = src;
    }
}

// ---------------- GEMM1: hs1h = fp16((x @ W1) * dinv), padded rows -----------
__global__ __launch_bounds__(256) void k_gemm1(const float* __restrict__ x,
                                               const float* __restrict__ W1) {
    __shared__ float Ws[F_IN * F_HID];                   // 12 KB
    __shared__ __align__(16) float xs[64 * F_IN];        // 32 KB
    int tid = threadIdx.x;
    for (int i = tid; i < F_IN * F_HID; i += 256) Ws[i] = W1[i];

    int base = blockIdx.x * 64;
    int nvalid = N_NODES - base; if (nvalid > 64) nvalid = 64;
    const float4* xv = (const float4*)(x + (size_t)base * F_IN);
    float4* xsv = (float4*)xs;
    int nv4 = nvalid * (F_IN / 4);
    for (int i = tid; i < nv4; i += 256) xsv[i] = xv[i];
    __syncthreads();

    int nloc = tid >> 2;                   // 0..63
    int l = tid & 3;
    int node = base + nloc;
    if (node >= N_NODES) return;

    float a[6] = {0.f, 0.f, 0.f, 0.f, 0.f, 0.f};
    const float* xr = xs + nloc * F_IN;
    #pragma unroll
    for (int k = 0; k < F_IN; k++) {
        float xk = xr[k];
        #pragma unroll
        for (int m = 0; m < 6; m++) a[m] = fmaf(xk, Ws[k * F_HID + l * 6 + m], a[m]);
    }
    float dv = g_dinv[node];
    __half2* o = (__half2*)(g_hs1h + (size_t)node * HID_PAD + l * 6);
    o[0] = __floats2half2_rn(a[0] * dv, a[1] * dv);
    o[1] = __floats2half2_rn(a[2] * dv, a[3] * dv);
    o[2] = __floats2half2_rn(a[4] * dv, a[5] * dv);
    if (l == 3) {                          // zero pad halfs [24..32)
        uint4 z = make_uint4(0u, 0u, 0u, 0u);
        *(uint4*)(g_hs1h + (size_t)node * HID_PAD + 24) = z;
    }
}

// fp32 accumulate of one fp16x8 vector
__device__ __forceinline__ void add8(float* acc, uint4 v) {
    __half2* hp = (__half2*)&v;
    #pragma unroll
    for (int c = 0; c < 4; c++) {
        float2 f = __half22float2(hp[c]);
        acc[2*c]   += f.x;
        acc[2*c+1] += f.y;
    }
}

// pairwise: fp16 add two vectors, convert pair-sum once, fp32 accumulate
__device__ __forceinline__ void add8p(float* acc, uint4 a, uint4 b) {
    __half2* pa = (__half2*)&a;
    __half2* pb = (__half2*)&b;
    #pragma unroll
    for (int c = 0; c < 4; c++) {
        float2 f = __half22float2(__hadd2(pa[c], pb[c]));
        acc[2*c]   += f.x;
        acc[2*c+1] += f.y;
    }
}

// ---------------- layer1 gather (4 lanes/node, pairwise fp16) + relu + GEMM2 -
__global__ __launch_bounds__(256) void k_gather1(const float* __restrict__ b1,
                                                 const float* __restrict__ W2) {
    __shared__ float W2s[F_HID * F_OUT];
    __shared__ float b1s[F_HID];
    int tid = threadIdx.x;
    for (int i = tid; i < F_HID * F_OUT; i += 256) W2s[i] = W2[i];
    if (tid < F_HID) b1s[tid] = b1[tid];
    __syncthreads();

    int lane = tid & 31;
    int l = lane & 3;                      // uint4 slot within 32-half row
    int node = blockIdx.x * 64 + (tid >> 2);
    int nc = (node < N_NODES) ? node : (N_NODES - 1);

    const uint4* base = (const uint4*)g_hs1h;    // row = 4 x uint4
    float acc[8];
    {
        uint4 sv = base[(size_t)nc * 4 + l];     // self-loop term
        __half2* hp = (__half2*)&sv;
        #pragma unroll
        for (int c = 0; c < 4; c++) {
            float2 f = __half22float2(hp[c]);
            acc[2*c] = f.x; acc[2*c+1] = f.y;
        }
    }
    int s = g_off[nc], e = g_off[nc + 1];
    int i = s;
    for (; i + 3 < e; i += 4) {            // 4 gathers in flight per lane
        int s0 = g_csr[i], s1 = g_csr[i+1], s2 = g_csr[i+2], s3 = g_csr[i+3];
        uint4 v0 = base[(size_t)s0 * 4 + l];
        uint4 v1 = base[(size_t)s1 * 4 + l];
        uint4 v2 = base[(size_t)s2 * 4 + l];
        uint4 v3 = base[(size_t)s3 * 4 + l];
        add8p(acc, v0, v1);
        add8p(acc, v2, v3);
    }
    if (i + 1 < e) {
        int s0 = g_csr[i], s1 = g_csr[i+1];
        add8p(acc, base[(size_t)s0 * 4 + l], base[(size_t)s1 * 4 + l]);
        i += 2;
    }
    if (i < e) add8(acc, base[(size_t)g_csr[i] * 4 + l]);

    float dv = g_dinv[nc];
    float h[8];
    if (l < 3) {
        #pragma unroll
        for (int k = 0; k < 8; k++)
            h[k] = fmaxf(fmaf(dv, acc[k], b1s[l * 8 + k]), 0.f);
    } else {
        #pragma unroll
        for (int k = 0; k < 8; k++) h[k] = 0.f;
    }

    // GEMM2: lane computes output cols 4l..4l+3; h broadcast via shuffles
    float o0 = 0.f, o1 = 0.f, o2 = 0.f, o3 = 0.f;
    int gbase = lane & ~3;
    #pragma unroll
    for (int j = 0; j < F_HID; j++) {
        float hj = __shfl_sync(0xffffffffu, h[j & 7], gbase + (j >> 3));
        o0 = fmaf(hj, W2s[j * F_OUT + l*4 + 0], o0);
        o1 = fmaf(hj, W2s[j * F_OUT + l*4 + 1], o1);
        o2 = fmaf(hj, W2s[j * F_OUT + l*4 + 2], o2);
        o3 = fmaf(hj, W2s[j * F_OUT + l*4 + 3], o3);
    }
    if (node < N_NODES) {
        __half2* op = (__half2*)(g_hs2h + (size_t)node * F_OUT + l * 4);
        op[0] = __floats2half2_rn(o0 * dv, o1 * dv);
        op[1] = __floats2half2_rn(o2 * dv, o3 * dv);
    }
}

// ---------------- layer2 gather (2 lanes/node, pairwise fp16) + log_softmax --
__global__ __launch_bounds__(256) void k_gather2(const float* __restrict__ b2,
                                                 float* __restrict__ out) {
    __shared__ float b2s[F_OUT];
    if (threadIdx.x < F_OUT) b2s[threadIdx.x] = b2[threadIdx.x];
    __syncthreads();

    int tid = threadIdx.x;
    int lane = tid & 31;
    int l = lane & 1;                      // uint4 slot within 16-half row
    int node = blockIdx.x * 128 + (tid >> 1);
    int nc = (node < N_NODES) ? node : (N_NODES - 1);

    const uint4* base = (const uint4*)g_hs2h;    // row = 2 x uint4
    float acc[8];
    {
        uint4 sv = base[(size_t)nc * 2 + l];
        __half2* hp = (__half2*)&sv;
        #pragma unroll
        for (int c = 0; c < 4; c++) {
            float2 f = __half22float2(hp[c]);
            acc[2*c] = f.x; acc[2*c+1] = f.y;
        }
    }
    int s = g_off[nc], e = g_off[nc + 1];
    int i = s;
    for (; i + 3 < e; i += 4) {
        int s0 = g_csr[i], s1 = g_csr[i+1], s2 = g_csr[i+2], s3 = g_csr[i+3];
        uint4 v0 = base[(size_t)s0 * 2 + l];
        uint4 v1 = base[(size_t)s1 * 2 + l];
        uint4 v2 = base[(size_t)s2 * 2 + l];
        uint4 v3 = base[(size_t)s3 * 2 + l];
        add8p(acc, v0, v1);
        add8p(acc, v2, v3);
    }
    if (i + 1 < e) {
        int s0 = g_csr[i], s1 = g_csr[i+1];
        add8p(acc, base[(size_t)s0 * 2 + l], base[(size_t)s1 * 2 + l]);
        i += 2;
    }
    if (i < e) add8(acc, base[(size_t)g_csr[i] * 2 + l]);

    float dv = g_dinv[nc];
    float z[8];
    #pragma unroll
    for (int k = 0; k < 8; k++) z[k] = fmaf(dv, acc[k], b2s[l * 8 + k]);

    float m = z[0];
    #pragma unroll
    for (int k = 1; k < 8; k++) m = fmaxf(m, z[k]);
    m = fmaxf(m, __shfl_xor_sync(0xffffffffu, m, 1));
    float sum = 0.f;
    #pragma unroll
    for (int k = 0; k < 8; k++) sum += __expf(z[k] - m);
    sum += __shfl_xor_sync(0xffffffffu, sum, 1);
    float lse = m + __logf(sum);

    if (node < N_NODES) {
        float4* outp = (float4*)out + (size_t)node * 4 + l * 2;
        float4 w0, w1;
        w0.x = z[0] - lse; w0.y = z[1] - lse; w0.z = z[2] - lse; w0.w = z[3] - lse;
        w1.x = z[4] - lse; w1.y = z[5] - lse; w1.z = z[6] - lse; w1.w = z[7] - lse;
        outp[0] = w0; outp[1] = w1;
    }
}

// ---------------- launch ------------------------------------------------------
extern "C" void kernel_launch(void* const* d_in, const int* in_sizes, int n_in,
                              void* d_out, int out_size) {
    const float* x  = (const float*)d_in[0];
    const void*  ei = d_in[1];
    const float* W1 = (const float*)d_in[2];
    const float* b1 = (const float*)d_in[3];
    const float* W2 = (const float*)d_in[4];
    const float* b2 = (const float*)d_in[5];
    float* out = (float*)d_out;

    int E = in_sizes[1] / 2;
    if (E > MAX_E) E = MAX_E;

    const int NB = (N_NODES + 255) / 256;     // 391
    const int EB = (E + 255) / 256;
    const int SB = (N_NODES + 1023) / 1024;   // 98

    k_detect_init<<<NB, 256>>>((const unsigned int*)ei);
    k_count_deg<<<EB, 256>>>(ei, E);
    k_scan_block<<<SB, 1024>>>(N_NODES);
    k_scan_add<<<NB, 256>>>(N_NODES, E);
    k_fill_csr<<<EB, 256>>>(ei, E);
    k_gemm1<<<(N_NODES + 63) / 64, 256>>>(x, W1);
    k_gather1<<<(N_NODES + 63) / 64, 256>>>(b1, W2);
    k_gather2<<<(N_NODES + 127) / 128, 256>>>(b2, out);
}